// round 2
// baseline (speedup 1.0000x reference)
#include <cuda_runtime.h>

#define NB 4
#define NT 8192
#define NC 128
#define NL 40
#define TILE 64
#define NTHREADS 256

// Persistent device scratch (allocation-free rule: __device__ globals)
__device__ float g_hA[NB * NT * NC];
__device__ float g_hB[NB * NT * NC];
__device__ float g_skip[NB * NT * NC];
__device__ float g_wconv[NL * 2 * NC * 2 * NC];  // [l][tap][c(128)][o(256)]
__device__ float g_wpost[NL * NC * NC];          // [l][c][o]
__device__ float g_lin[2][NC * NC];              // [which][i][o]

// ---------------- weight transposes (run every launch; deterministic) -------

__global__ void tconv_kernel(const float* __restrict__ w) {
    // w: [L][256][128][2] -> g_wconv [l][tap][c][o]
    int idx = blockIdx.x * blockDim.x + threadIdx.x;  // exact: NL*256*128*2
    int tap = idx & 1;
    int c = (idx >> 1) & 127;
    int o = (idx >> 8) & 255;
    int l = idx >> 16;
    g_wconv[((l * 2 + tap) * 128 + c) * 256 + o] = w[idx];
}

__global__ void tpost_kernel(const float* __restrict__ w) {
    // w: [L][128 o][128 c] -> [l][c][o]
    int idx = blockIdx.x * blockDim.x + threadIdx.x;  // exact: NL*128*128
    int c = idx & 127;
    int o = (idx >> 7) & 127;
    int l = idx >> 14;
    g_wpost[(l * 128 + c) * 128 + o] = w[idx];
}

__global__ void tlin_kernel(const float* __restrict__ w, int which) {
    // w: [128 o][128 i] -> [i][o]
    int idx = blockIdx.x * blockDim.x + threadIdx.x;  // exact: 128*128
    int i = idx & 127;
    int o = idx >> 7;
    g_lin[which][i * 128 + o] = w[idx];
}

// ---------------- pre-net: causal conv1d k=3, 1 -> 128 channels -------------

__global__ void pre_kernel(const float* __restrict__ x,
                           const float* __restrict__ w,
                           const float* __restrict__ b) {
    int bt = blockIdx.x;       // b*NT + t
    int bb = bt >> 13;         // / 8192
    int t = bt & 8191;
    int c = threadIdx.x;
    const float* xb = x + bb * NT;
    float x0 = (t >= 2) ? xb[t - 2] : 0.f;
    float x1 = (t >= 1) ? xb[t - 1] : 0.f;
    float x2 = xb[t];
    g_hA[bt * NC + c] = w[c * 3 + 0] * x0 + w[c * 3 + 1] * x1 + w[c * 3 + 2] * x2 + b[c];
}

// ---------------- fused WaveNet block --------------------------------------
// y = W0 @ h[t-d] + W1 @ h[t] + cb ; skip = y[:128] * sigmoid(y[128:])
// h' = h + Wp @ skip + pb ; skip_sum (+)= skip

__global__ void __launch_bounds__(NTHREADS, 2)
layer_kernel(int l, int dil, int flip, int first,
             const float* __restrict__ conv_b,
             const float* __restrict__ post_b) {
    const float* __restrict__ h_in = flip ? g_hB : g_hA;
    float* __restrict__ h_out = flip ? g_hA : g_hB;

    extern __shared__ float sm[];
    float* Xc = sm;             // [64][128] current h tile
    float* Xp = sm + 8192;      // [64][128] prev (t-d) tile, reused as skip tile
    float* Wc = sm + 16384;     // [2 taps][8 k][256 o]
    float* Wp = sm + 20480;     // [8 k][128 o]

    int tid = threadIdx.x;
    int o_idx = tid & 31;
    int t_idx = tid >> 5;
    int c0 = o_idx * 4;
    int tr0 = t_idx * 8;

    int b = blockIdx.x >> 7;             // 128 tiles per batch
    int t0 = (blockIdx.x & 127) * TILE;
    const float* hin_t = h_in + (b * NT + t0) * NC;

    // stage Xc
    {
        const float4* src = (const float4*)hin_t;
        float4* dst = (float4*)Xc;
#pragma unroll
        for (int i = 0; i < 8; ++i) dst[tid + i * 256] = src[tid + i * 256];
    }
    // stage Xp (rows t0-d .. t0-d+63, zero for t<0)
    {
        int tp0 = t0 - dil;
        float4* dst = (float4*)Xp;
        const float4* base = (const float4*)(h_in + b * NT * NC);
#pragma unroll
        for (int i = 0; i < 8; ++i) {
            int e = tid + i * 256;
            int row = e >> 5;            // 32 float4 per row
            int tp = tp0 + row;
            float4 v = make_float4(0.f, 0.f, 0.f, 0.f);
            if (tp >= 0) v = base[tp * 32 + (e & 31)];
            dst[e] = v;
        }
    }

    const float* wconv_l = g_wconv + l * 65536;

    float acc[8][8];
#pragma unroll
    for (int r = 0; r < 8; ++r)
#pragma unroll
        for (int t = 0; t < 8; ++t) acc[r][t] = 0.f;

    // ---- conv GEMM: M=256(o), N=64(t), K=128, 2 taps, K chunked by 8 ----
    for (int kc = 0; kc < 16; ++kc) {
        __syncthreads();
        {
            const float4* s0 = (const float4*)(wconv_l + kc * 2048);
            const float4* s1 = (const float4*)(wconv_l + 32768 + kc * 2048);
            float4* d0 = (float4*)Wc;
            float4* d1 = (float4*)(Wc + 2048);
            d0[tid] = s0[tid];
            d0[tid + 256] = s0[tid + 256];
            d1[tid] = s1[tid];
            d1[tid + 256] = s1[tid + 256];
        }
        __syncthreads();
#pragma unroll
        for (int k = 0; k < 8; ++k) {
            float4 w0a = *(float4*)&Wc[k * 256 + c0];
            float4 w0b = *(float4*)&Wc[k * 256 + 128 + c0];
            float4 w1a = *(float4*)&Wc[2048 + k * 256 + c0];
            float4 w1b = *(float4*)&Wc[2048 + k * 256 + 128 + c0];
            int kk = kc * 8 + k;
#pragma unroll
            for (int t = 0; t < 8; ++t) {
                float xp = Xp[(tr0 + t) * NC + kk];
                float xc = Xc[(tr0 + t) * NC + kk];
                acc[0][t] = fmaf(w0a.x, xp, acc[0][t]);
                acc[1][t] = fmaf(w0a.y, xp, acc[1][t]);
                acc[2][t] = fmaf(w0a.z, xp, acc[2][t]);
                acc[3][t] = fmaf(w0a.w, xp, acc[3][t]);
                acc[4][t] = fmaf(w0b.x, xp, acc[4][t]);
                acc[5][t] = fmaf(w0b.y, xp, acc[5][t]);
                acc[6][t] = fmaf(w0b.z, xp, acc[6][t]);
                acc[7][t] = fmaf(w0b.w, xp, acc[7][t]);
                acc[0][t] = fmaf(w1a.x, xc, acc[0][t]);
                acc[1][t] = fmaf(w1a.y, xc, acc[1][t]);
                acc[2][t] = fmaf(w1a.z, xc, acc[2][t]);
                acc[3][t] = fmaf(w1a.w, xc, acc[3][t]);
                acc[4][t] = fmaf(w1b.x, xc, acc[4][t]);
                acc[5][t] = fmaf(w1b.y, xc, acc[5][t]);
                acc[6][t] = fmaf(w1b.z, xc, acc[6][t]);
                acc[7][t] = fmaf(w1b.w, xc, acc[7][t]);
            }
        }
    }

    // ---- GLU (pairs held in-thread) + skip_sum ----
    float4 cba = *(const float4*)(conv_b + l * 256 + c0);
    float4 cbb = *(const float4*)(conv_b + l * 256 + 128 + c0);
    float sk[4][8];
#pragma unroll
    for (int t = 0; t < 8; ++t) {
        float a0 = acc[0][t] + cba.x, a1 = acc[1][t] + cba.y;
        float a2 = acc[2][t] + cba.z, a3 = acc[3][t] + cba.w;
        float g0 = acc[4][t] + cbb.x, g1 = acc[5][t] + cbb.y;
        float g2 = acc[6][t] + cbb.z, g3 = acc[7][t] + cbb.w;
        sk[0][t] = a0 * (1.f / (1.f + __expf(-g0)));
        sk[1][t] = a1 * (1.f / (1.f + __expf(-g1)));
        sk[2][t] = a2 * (1.f / (1.f + __expf(-g2)));
        sk[3][t] = a3 * (1.f / (1.f + __expf(-g3)));
    }

    __syncthreads();  // all conv reads of Xp done; reuse as skip tile

    float* gsk = g_skip + (b * NT + t0) * NC;
#pragma unroll
    for (int t = 0; t < 8; ++t) {
        float4 s4 = make_float4(sk[0][t], sk[1][t], sk[2][t], sk[3][t]);
        *(float4*)&Xp[(tr0 + t) * NC + c0] = s4;
        float4* gp = (float4*)&gsk[(tr0 + t) * NC + c0];
        if (first) {
            *gp = s4;
        } else {
            float4 o = *gp;
            o.x += s4.x; o.y += s4.y; o.z += s4.z; o.w += s4.w;
            *gp = o;
        }
    }

    // ---- post GEMM: h' = h + Wp @ skip + pb ----
    const float* wpost_l = g_wpost + l * 16384;
    float accp[4][8];
#pragma unroll
    for (int r = 0; r < 4; ++r)
#pragma unroll
        for (int t = 0; t < 8; ++t) accp[r][t] = 0.f;

    for (int kc = 0; kc < 16; ++kc) {
        __syncthreads();
        ((float4*)Wp)[tid] = ((const float4*)(wpost_l + kc * 1024))[tid];
        __syncthreads();
#pragma unroll
        for (int k = 0; k < 8; ++k) {
            float4 w4 = *(float4*)&Wp[k * 128 + c0];
            int kk = kc * 8 + k;
#pragma unroll
            for (int t = 0; t < 8; ++t) {
                float sv = Xp[(tr0 + t) * NC + kk];
                accp[0][t] = fmaf(w4.x, sv, accp[0][t]);
                accp[1][t] = fmaf(w4.y, sv, accp[1][t]);
                accp[2][t] = fmaf(w4.z, sv, accp[2][t]);
                accp[3][t] = fmaf(w4.w, sv, accp[3][t]);
            }
        }
    }

    float4 pb = *(const float4*)(post_b + l * 128 + c0);
    float* hout_t = h_out + (b * NT + t0) * NC;
#pragma unroll
    for (int t = 0; t < 8; ++t) {
        float4 hv = *(float4*)&Xc[(tr0 + t) * NC + c0];
        float4 ov;
        ov.x = hv.x + accp[0][t] + pb.x;
        ov.y = hv.y + accp[1][t] + pb.y;
        ov.z = hv.z + accp[2][t] + pb.z;
        ov.w = hv.w + accp[3][t] + pb.w;
        *(float4*)&hout_t[(tr0 + t) * NC + c0] = ov;
    }
}

// ---------------- final: relu -> lin1 -> relu -> lin2 -----------------------

__global__ void __launch_bounds__(NTHREADS, 2)
final_kernel(const float* __restrict__ lin1_b,
             const float* __restrict__ lin2_b,
             float* __restrict__ out) {
    extern __shared__ float sm[];
    float* Z = sm;            // [64][128]
    float* Z2 = sm + 8192;    // [64][128]
    float* Wl = sm + 16384;   // [8][128]

    int tid = threadIdx.x;
    int o_idx = tid & 31;
    int t_idx = tid >> 5;
    int c0 = o_idx * 4;
    int tr0 = t_idx * 8;

    int b = blockIdx.x >> 7;
    int t0 = (blockIdx.x & 127) * TILE;

    {
        const float4* src = (const float4*)(g_skip + (b * NT + t0) * NC);
        float4* dst = (float4*)Z;
#pragma unroll
        for (int i = 0; i < 8; ++i) {
            float4 v = src[tid + i * 256];
            v.x = fmaxf(v.x, 0.f); v.y = fmaxf(v.y, 0.f);
            v.z = fmaxf(v.z, 0.f); v.w = fmaxf(v.w, 0.f);
            dst[tid + i * 256] = v;
        }
    }

    float acc[4][8];
#pragma unroll
    for (int r = 0; r < 4; ++r)
#pragma unroll
        for (int t = 0; t < 8; ++t) acc[r][t] = 0.f;

    for (int kc = 0; kc < 16; ++kc) {
        __syncthreads();
        ((float4*)Wl)[tid] = ((const float4*)(g_lin[0] + kc * 1024))[tid];
        __syncthreads();
#pragma unroll
        for (int k = 0; k < 8; ++k) {
            float4 w4 = *(float4*)&Wl[k * 128 + c0];
            int kk = kc * 8 + k;
#pragma unroll
            for (int t = 0; t < 8; ++t) {
                float zv = Z[(tr0 + t) * NC + kk];
                acc[0][t] = fmaf(w4.x, zv, acc[0][t]);
                acc[1][t] = fmaf(w4.y, zv, acc[1][t]);
                acc[2][t] = fmaf(w4.z, zv, acc[2][t]);
                acc[3][t] = fmaf(w4.w, zv, acc[3][t]);
            }
        }
    }

    float4 b1 = *(const float4*)(lin1_b + c0);
#pragma unroll
    for (int t = 0; t < 8; ++t) {
        float4 z2;
        z2.x = fmaxf(acc[0][t] + b1.x, 0.f);
        z2.y = fmaxf(acc[1][t] + b1.y, 0.f);
        z2.z = fmaxf(acc[2][t] + b1.z, 0.f);
        z2.w = fmaxf(acc[3][t] + b1.w, 0.f);
        *(float4*)&Z2[(tr0 + t) * NC + c0] = z2;
    }

    float acc2[4][8];
#pragma unroll
    for (int r = 0; r < 4; ++r)
#pragma unroll
        for (int t = 0; t < 8; ++t) acc2[r][t] = 0.f;

    for (int kc = 0; kc < 16; ++kc) {
        __syncthreads();
        ((float4*)Wl)[tid] = ((const float4*)(g_lin[1] + kc * 1024))[tid];
        __syncthreads();
#pragma unroll
        for (int k = 0; k < 8; ++k) {
            float4 w4 = *(float4*)&Wl[k * 128 + c0];
            int kk = kc * 8 + k;
#pragma unroll
            for (int t = 0; t < 8; ++t) {
                float zv = Z2[(tr0 + t) * NC + kk];
                acc2[0][t] = fmaf(w4.x, zv, acc2[0][t]);
                acc2[1][t] = fmaf(w4.y, zv, acc2[1][t]);
                acc2[2][t] = fmaf(w4.z, zv, acc2[2][t]);
                acc2[3][t] = fmaf(w4.w, zv, acc2[3][t]);
            }
        }
    }

    float4 b2 = *(const float4*)(lin2_b + c0);
#pragma unroll
    for (int t = 0; t < 8; ++t) {
        float4 ov;
        ov.x = acc2[0][t] + b2.x;
        ov.y = acc2[1][t] + b2.y;
        ov.z = acc2[2][t] + b2.z;
        ov.w = acc2[3][t] + b2.w;
        // out layout: [T][B][C]
        *(float4*)&out[((t0 + tr0 + t) * NB + b) * NC + c0] = ov;
    }
}

// ---------------- launch -----------------------------------------------------

extern "C" void kernel_launch(void* const* d_in, const int* in_sizes, int n_in,
                              void* d_out, int out_size) {
    const float* x      = (const float*)d_in[0];
    const float* pre_w  = (const float*)d_in[1];
    const float* pre_b  = (const float*)d_in[2];
    const float* conv_w = (const float*)d_in[3];
    const float* conv_b = (const float*)d_in[4];
    const float* post_w = (const float*)d_in[5];
    const float* post_b = (const float*)d_in[6];
    const float* lin1_w = (const float*)d_in[7];
    const float* lin1_b = (const float*)d_in[8];
    const float* lin2_w = (const float*)d_in[9];
    const float* lin2_b = (const float*)d_in[10];

    cudaFuncSetAttribute(layer_kernel, cudaFuncAttributeMaxDynamicSharedMemorySize, 86016);
    cudaFuncSetAttribute(final_kernel, cudaFuncAttributeMaxDynamicSharedMemorySize, 69632);

    // weight transposes (cheap, deterministic each launch)
    tconv_kernel<<<10240, 256>>>(conv_w);   // 40*256*128*2 / 256
    tpost_kernel<<<2560, 256>>>(post_w);    // 40*128*128 / 256
    tlin_kernel<<<64, 256>>>(lin1_w, 0);
    tlin_kernel<<<64, 256>>>(lin2_w, 1);

    pre_kernel<<<NB * NT, 128>>>(x, pre_w, pre_b);

    for (int i = 0; i < NL; ++i) {
        int d = 1 << (i % 10);
        layer_kernel<<<512, NTHREADS, 86016>>>(i, d, i & 1, (i == 0) ? 1 : 0,
                                               conv_b, post_b);
    }

    final_kernel<<<512, NTHREADS, 69632>>>(lin1_b, lin2_b, (float*)d_out);
}